// round 2
// baseline (speedup 1.0000x reference)
#include <cuda_runtime.h>

// ParallelSubPolicies: 64 independent MLPs (128->256->256->256->32),
// GroupNorm (one group = full feature dim) + ELU after layers 1-3,
// GroupNorm only after layer 4. B=4096 shared observations.
//
// Fused design: grid = (B/64, P). Each CTA owns one policy p and a 64-row
// batch tile. Activations stay in SMEM across all 4 layers. Weights are
// streamed from global (L2-resident, 44MB total) through a 16xN SMEM chunk
// with register prefetch. 256 threads; per-thread 4x16 fp32 register tile.
// GroupNorm row stats via 16-lane butterfly shuffle.

#define OBSD 128
#define ACTD 32
#define HIDD 256
#define NP   64
#define NB   4096
#define TB   64
#define XST  (HIDD + 4)      // padded activation row stride (bank-conflict free)
#define EPSV 1e-5f
#define SMEM_FLOATS (TB * XST + 16 * HIDD)

template<int K, int N, bool DO_ACT, bool FINAL>
__device__ __forceinline__ void layer_run(
    float* xs, float* wbuf,
    const float* __restrict__ Wp, const float* __restrict__ bv,
    const float* __restrict__ gv, const float* __restrict__ bev,
    float* __restrict__ outp)
{
    constexpr int CN = N / 16;               // cols per thread (16 or 2)
    const int tid  = threadIdx.x;
    const int c    = tid & 15;
    const int r    = tid >> 4;
    const int col0 = c * CN;
    const int row0 = r * 4;

    float acc[4][CN];
#pragma unroll
    for (int i = 0; i < 4; i++)
#pragma unroll
        for (int j = 0; j < CN; j++) acc[i][j] = 0.f;

    constexpr int LD4 = (16 * N) / 4;        // float4 loads per chunk
    constexpr int PT  = (LD4 + 255) / 256;   // per-thread prefetch regs
    float4 pf[PT];

    // prefetch chunk 0
#pragma unroll
    for (int t = 0; t < PT; t++) {
        int idx = tid + t * 256;
        if (idx < LD4) pf[t] = reinterpret_cast<const float4*>(Wp)[idx];
    }

    for (int k0 = 0; k0 < K; k0 += 16) {
        __syncthreads();                     // wbuf consumers from prev chunk done
#pragma unroll
        for (int t = 0; t < PT; t++) {
            int idx = tid + t * 256;
            if (idx < LD4) reinterpret_cast<float4*>(wbuf)[idx] = pf[t];
        }
        __syncthreads();
        if (k0 + 16 < K) {                   // prefetch next chunk (overlaps compute)
#pragma unroll
            for (int t = 0; t < PT; t++) {
                int idx = tid + t * 256;
                if (idx < LD4)
                    pf[t] = reinterpret_cast<const float4*>(Wp + (size_t)(k0 + 16) * N)[idx];
            }
        }
#pragma unroll
        for (int kk = 0; kk < 16; kk++) {
            float xv[4];
#pragma unroll
            for (int i = 0; i < 4; i++) xv[i] = xs[(row0 + i) * XST + k0 + kk];
            float wv[CN];
            if constexpr (CN >= 4) {
#pragma unroll
                for (int j = 0; j < CN; j += 4) {
                    float4 w4 = *reinterpret_cast<const float4*>(wbuf + kk * N + col0 + j);
                    wv[j] = w4.x; wv[j + 1] = w4.y; wv[j + 2] = w4.z; wv[j + 3] = w4.w;
                }
            } else {
                float2 w2 = *reinterpret_cast<const float2*>(wbuf + kk * N + col0);
                wv[0] = w2.x; wv[1] = w2.y;
            }
#pragma unroll
            for (int i = 0; i < 4; i++)
#pragma unroll
                for (int j = 0; j < CN; j++)
                    acc[i][j] = fmaf(xv[i], wv[j], acc[i][j]);
        }
    }
    __syncthreads();   // all xs reads complete before epilogue overwrites xs

    const float invn = 1.f / (float)N;
#pragma unroll
    for (int i = 0; i < 4; i++) {
        float s1 = 0.f, s2 = 0.f;
#pragma unroll
        for (int j = 0; j < CN; j++) {
            float y = acc[i][j] + bv[col0 + j];
            acc[i][j] = y;
            s1 += y;
            s2 = fmaf(y, y, s2);
        }
        // reduce across the 16 lanes sharing this row
#pragma unroll
        for (int m = 1; m < 16; m <<= 1) {
            s1 += __shfl_xor_sync(0xffffffffu, s1, m);
            s2 += __shfl_xor_sync(0xffffffffu, s2, m);
        }
        float mean = s1 * invn;
        float var  = fmaf(-mean, mean, s2 * invn);
        float rstd = rsqrtf(var + EPSV);
#pragma unroll
        for (int j = 0; j < CN; j++) {
            float y = (acc[i][j] - mean) * rstd * gv[col0 + j] + bev[col0 + j];
            if (DO_ACT) y = (y > 0.f) ? y : expm1f(y);
            acc[i][j] = y;
        }
        if constexpr (FINAL) {
#pragma unroll
            for (int j = 0; j < CN; j++)
                outp[(size_t)(row0 + i) * (NP * ACTD) + col0 + j] = acc[i][j];
        } else {
#pragma unroll
            for (int j = 0; j < CN; j++)
                xs[(row0 + i) * XST + col0 + j] = acc[i][j];
        }
    }
    // next layer's first __syncthreads orders these writes before its reads
}

__global__ __launch_bounds__(256, 2)
void ParallelSubPolicies_kernel(
    const float* __restrict__ obs,
    const float* __restrict__ W1, const float* __restrict__ b1,
    const float* __restrict__ g1, const float* __restrict__ be1,
    const float* __restrict__ W2, const float* __restrict__ b2,
    const float* __restrict__ g2, const float* __restrict__ be2,
    const float* __restrict__ W3, const float* __restrict__ b3,
    const float* __restrict__ g3, const float* __restrict__ be3,
    const float* __restrict__ W4, const float* __restrict__ b4,
    const float* __restrict__ g4, const float* __restrict__ be4,
    float* __restrict__ out)
{
    extern __shared__ float smem[];
    float* xs   = smem;                 // [TB][XST]
    float* wbuf = smem + TB * XST;      // [16][N] flat

    const int p   = blockIdx.y;
    const int r0  = blockIdx.x * TB;
    const int tid = threadIdx.x;

    // stage observation tile into xs[:, 0:128]
    for (int idx = tid; idx < TB * (OBSD / 4); idx += 256) {
        int row = idx / (OBSD / 4);
        int c4  = idx % (OBSD / 4);
        float4 v = reinterpret_cast<const float4*>(obs)[(size_t)(r0 + row) * (OBSD / 4) + c4];
        *reinterpret_cast<float4*>(xs + row * XST + c4 * 4) = v;
    }
    // layer_run's internal __syncthreads orders staging before first reads

    layer_run<OBSD, HIDD, true,  false>(xs, wbuf,
        W1 + (size_t)p * OBSD * HIDD, b1 + p * HIDD, g1 + p * HIDD, be1 + p * HIDD, nullptr);
    layer_run<HIDD, HIDD, true,  false>(xs, wbuf,
        W2 + (size_t)p * HIDD * HIDD, b2 + p * HIDD, g2 + p * HIDD, be2 + p * HIDD, nullptr);
    layer_run<HIDD, HIDD, true,  false>(xs, wbuf,
        W3 + (size_t)p * HIDD * HIDD, b3 + p * HIDD, g3 + p * HIDD, be3 + p * HIDD, nullptr);
    layer_run<HIDD, ACTD, false, true >(xs, wbuf,
        W4 + (size_t)p * HIDD * ACTD, b4 + p * ACTD, g4 + p * ACTD, be4 + p * ACTD,
        out + (size_t)r0 * NP * ACTD + (size_t)p * ACTD);
}

extern "C" void kernel_launch(void* const* d_in, const int* in_sizes, int n_in,
                              void* d_out, int out_size)
{
    const float* obs = (const float*)d_in[0];
    const float* W1  = (const float*)d_in[1];
    const float* b1  = (const float*)d_in[2];
    const float* g1  = (const float*)d_in[3];
    const float* be1 = (const float*)d_in[4];
    const float* W2  = (const float*)d_in[5];
    const float* b2  = (const float*)d_in[6];
    const float* g2  = (const float*)d_in[7];
    const float* be2 = (const float*)d_in[8];
    const float* W3  = (const float*)d_in[9];
    const float* b3  = (const float*)d_in[10];
    const float* g3  = (const float*)d_in[11];
    const float* be3 = (const float*)d_in[12];
    const float* W4  = (const float*)d_in[13];
    const float* b4  = (const float*)d_in[14];
    const float* g4  = (const float*)d_in[15];
    const float* be4 = (const float*)d_in[16];
    float* out = (float*)d_out;

    size_t smem_bytes = SMEM_FLOATS * sizeof(float);
    cudaFuncSetAttribute(ParallelSubPolicies_kernel,
                         cudaFuncAttributeMaxDynamicSharedMemorySize, (int)smem_bytes);

    dim3 grid(NB / TB, NP);
    ParallelSubPolicies_kernel<<<grid, 256, smem_bytes>>>(
        obs, W1, b1, g1, be1, W2, b2, g2, be2,
        W3, b3, g3, be3, W4, b4, g4, be4, out);
}

// round 4
// speedup vs baseline: 3.1570x; 3.1570x over previous
#include <cuda_runtime.h>
#include <cuda_bf16.h>
#include <cstdint>

#define OBSD 128
#define ACTD 32
#define HIDD 256
#define NP   64
#define NB   4096
#define MT   128
#define EPSV 1e-5f

// ---------------- SMEM layout (bytes) ----------------
#define AFRAG_HI 0          // 8 mtiles x 16 ktiles x 32 lanes x 16B = 64KB
#define AFRAG_LO 65536
#define PAR_OFF  131072     // 768 floats (bias | gamma | beta)
#define RED1_OFF 134144     // 8*128 floats
#define RED2_OFF 138240     // 8*128 floats
#define DSMEM_BYTES 142336

// ---------------- weight fragment image ----------------
#define L1_BYTES ((size_t)OBSD*HIDD*4)   // per-policy bytes (hi+lo bf16 = 4B/elem)
#define L2_BYTES ((size_t)HIDD*HIDD*4)
#define L4_BYTES ((size_t)HIDD*ACTD*4)
#define OFF_L1 0ull
#define OFF_L2 (OFF_L1 + 64ull*L1_BYTES)
#define OFF_L3 (OFF_L2 + 64ull*L2_BYTES)
#define OFF_L4 (OFF_L3 + 64ull*L2_BYTES)
#define WIMG_TOTAL (OFF_L4 + 64ull*L4_BYTES)

__device__ __align__(128) unsigned char g_wimg[WIMG_TOTAL];

// ---------------- helpers ----------------
__device__ __forceinline__ void mma16816(float* c, const uint4& a, uint32_t b0, uint32_t b1) {
    asm volatile(
        "mma.sync.aligned.m16n8k16.row.col.f32.bf16.bf16.f32 "
        "{%0,%1,%2,%3}, {%4,%5,%6,%7}, {%8,%9}, {%0,%1,%2,%3};"
        : "+f"(c[0]), "+f"(c[1]), "+f"(c[2]), "+f"(c[3])
        : "r"(a.x), "r"(a.y), "r"(a.z), "r"(a.w), "r"(b0), "r"(b1));
}

__device__ __forceinline__ void split_pack(float y0, float y1, uint32_t& hp, uint32_t& lp) {
    __nv_bfloat16 h0 = __float2bfloat16_rn(y0);
    __nv_bfloat16 h1 = __float2bfloat16_rn(y1);
    __nv_bfloat16 l0 = __float2bfloat16_rn(y0 - __bfloat162float(h0));
    __nv_bfloat16 l1 = __float2bfloat16_rn(y1 - __bfloat162float(h1));
    hp = (uint32_t)__bfloat16_as_ushort(h0) | ((uint32_t)__bfloat16_as_ushort(h1) << 16);
    lp = (uint32_t)__bfloat16_as_ushort(l0) | ((uint32_t)__bfloat16_as_ushort(l1) << 16);
}

__device__ __forceinline__ float elu1(float y) { return y > 0.f ? y : expm1f(y); }

// ---------------- weight preprocess ----------------
// W [P][K][N] fp32 -> per-(kt,nt) HMMA B-fragments, lane-contiguous:
// frag[kt][nt][lane] = {hi_r0, hi_r1, lo_r0, lo_r1} (uint4), where reg r holds
// B(k,n) bf16 pair: k = kt*16 + (lane%4)*2 + {0,1} + 8r, n = nt*8 + lane/4.
template<int N, int K>
__global__ void prep_kernel(const float* __restrict__ W, size_t off)
{
    __shared__ float tile[16 * N];
    const int p = blockIdx.x, kt = blockIdx.y;
    const int tid = threadIdx.x;
    const float4* src = reinterpret_cast<const float4*>(W + ((size_t)p * K + (size_t)kt * 16) * N);
    constexpr int NL4 = 16 * N / 4;
    for (int i = tid; i < NL4; i += 256)
        reinterpret_cast<float4*>(tile)[i] = src[i];
    __syncthreads();
    constexpr int NT = N / 8;
    uint4* dst = reinterpret_cast<uint4*>(g_wimg + off + (size_t)p * ((size_t)K * N * 4));
    for (int u = tid; u < NT * 32; u += 256) {
        int nt = u >> 5, lane = u & 31;
        int n = nt * 8 + (lane >> 2), q = (lane & 3) * 2;
        uint32_t hp[2], lp[2];
#pragma unroll
        for (int r = 0; r < 2; r++) {
            float w0 = tile[(q + 8 * r) * N + n];
            float w1 = tile[(q + 8 * r + 1) * N + n];
            __nv_bfloat16 h0 = __float2bfloat16_rn(w0);
            __nv_bfloat16 h1 = __float2bfloat16_rn(w1);
            __nv_bfloat16 l0 = __float2bfloat16_rn(w0 - __bfloat162float(h0));
            __nv_bfloat16 l1 = __float2bfloat16_rn(w1 - __bfloat162float(h1));
            hp[r] = (uint32_t)__bfloat16_as_ushort(h0) | ((uint32_t)__bfloat16_as_ushort(h1) << 16);
            lp[r] = (uint32_t)__bfloat16_as_ushort(l0) | ((uint32_t)__bfloat16_as_ushort(l1) << 16);
        }
        uint4 v; v.x = hp[0]; v.y = hp[1]; v.z = lp[0]; v.w = lp[1];
        dst[((size_t)kt * NT + nt) * 32 + lane] = v;
    }
}

// ---------------- fused main kernel ----------------
// A-fragment smem layout: idx(m,k) -> uint32 slot
//   mtile=m/16, ktile=k/16, a_lane=(m%8)*4+((k%8)/2), r=2*((k%16)>=8)+((m%16)>=8)
//   idx = ((mtile*16 + ktile)*32 + a_lane)*4 + r

template<int K, bool ACT>
__device__ __forceinline__ void hidden_layer(
    unsigned char* smem,
    const uint4* __restrict__ bfr,
    const float* __restrict__ bv, const float* __restrict__ gv, const float* __restrict__ bev,
    int tid)
{
    const int lane = tid & 31;
    const int wn   = tid >> 5;   // 8 N-warps: cols [wn*32, wn*32+32)
    uint32_t* ah = reinterpret_cast<uint32_t*>(smem + AFRAG_HI);
    uint32_t* al = reinterpret_cast<uint32_t*>(smem + AFRAG_LO);
    float* par  = reinterpret_cast<float*>(smem + PAR_OFF);
    float* red1 = reinterpret_cast<float*>(smem + RED1_OFF);
    float* red2 = reinterpret_cast<float*>(smem + RED2_OFF);

    for (int i = tid; i < 768; i += 256)
        par[i] = (i < 256) ? bv[i] : (i < 512 ? gv[i - 256] : bev[i - 512]);

    float acc[8][4][4];
#pragma unroll
    for (int mt = 0; mt < 8; mt++)
#pragma unroll
        for (int nt = 0; nt < 4; nt++)
#pragma unroll
            for (int r = 0; r < 4; r++) acc[mt][nt][r] = 0.f;

    constexpr int KTN = K / 16;
#pragma unroll 1
    for (int kt = 0; kt < KTN; kt++) {
        uint4 B[4];
#pragma unroll
        for (int nt = 0; nt < 4; nt++)
            B[nt] = __ldg(&bfr[((size_t)kt * 32 + wn * 4 + nt) * 32 + lane]);
#pragma unroll
        for (int half = 0; half < 2; half++) {
            uint4 Ah[4], Al[4];
#pragma unroll
            for (int q = 0; q < 4; q++) {
                int mg = half * 4 + q;
                Ah[q] = reinterpret_cast<const uint4*>(ah)[(mg * 16 + kt) * 32 + lane];
                Al[q] = reinterpret_cast<const uint4*>(al)[(mg * 16 + kt) * 32 + lane];
            }
#pragma unroll
            for (int q = 0; q < 4; q++) {
                int mt = half * 4 + q;
#pragma unroll
                for (int nt = 0; nt < 4; nt++) {
                    mma16816(acc[mt][nt], Ah[q], B[nt].x, B[nt].y);  // hi*hi
                    mma16816(acc[mt][nt], Ah[q], B[nt].z, B[nt].w);  // hi*lo
                    mma16816(acc[mt][nt], Al[q], B[nt].x, B[nt].y);  // lo*hi
                }
            }
        }
    }
    __syncthreads();   // A reads done everywhere; par visible

    // bias + per-row partial sums (this warp's 32-col slice)
#pragma unroll
    for (int mt = 0; mt < 8; mt++) {
        float s1a = 0.f, s2a = 0.f, s1b = 0.f, s2b = 0.f;
#pragma unroll
        for (int nt = 0; nt < 4; nt++) {
            int n0 = wn * 32 + nt * 8 + (lane & 3) * 2;
            float b0 = par[n0], b1 = par[n0 + 1];
            float y0 = acc[mt][nt][0] + b0, y1 = acc[mt][nt][1] + b1;
            float y2 = acc[mt][nt][2] + b0, y3 = acc[mt][nt][3] + b1;
            acc[mt][nt][0] = y0; acc[mt][nt][1] = y1;
            acc[mt][nt][2] = y2; acc[mt][nt][3] = y3;
            s1a += y0 + y1; s2a = fmaf(y0, y0, fmaf(y1, y1, s2a));
            s1b += y2 + y3; s2b = fmaf(y2, y2, fmaf(y3, y3, s2b));
        }
        s1a += __shfl_xor_sync(~0u, s1a, 1); s1a += __shfl_xor_sync(~0u, s1a, 2);
        s2a += __shfl_xor_sync(~0u, s2a, 1); s2a += __shfl_xor_sync(~0u, s2a, 2);
        s1b += __shfl_xor_sync(~0u, s1b, 1); s1b += __shfl_xor_sync(~0u, s1b, 2);
        s2b += __shfl_xor_sync(~0u, s2b, 1); s2b += __shfl_xor_sync(~0u, s2b, 2);
        if ((lane & 3) == 0) {
            int m0 = mt * 16 + (lane >> 2);
            red1[wn * 128 + m0]     = s1a; red2[wn * 128 + m0]     = s2a;
            red1[wn * 128 + m0 + 8] = s1b; red2[wn * 128 + m0 + 8] = s2b;
        }
    }
    __syncthreads();
    if (tid < 128) {
        float t1 = 0.f, t2 = 0.f;
#pragma unroll
        for (int w = 0; w < 8; w++) { t1 += red1[w * 128 + tid]; t2 += red2[w * 128 + tid]; }
        float mean = t1 * (1.f / 256.f);
        float var  = fmaf(-mean, mean, t2 * (1.f / 256.f));
        float rstd = rsqrtf(var + EPSV);
        red1[tid] = mean; red2[tid] = rstd;    // slot [0,128) only read by this thread above
    }
    __syncthreads();

    // normalize + activation + write next layer's A-fragments
#pragma unroll
    for (int mt = 0; mt < 8; mt++) {
        int mA = mt * 16 + (lane >> 2);
        float meanA = red1[mA],     rstdA = red2[mA];
        float meanB = red1[mA + 8], rstdB = red2[mA + 8];
#pragma unroll
        for (int nt = 0; nt < 4; nt++) {
            int n0 = wn * 32 + nt * 8 + (lane & 3) * 2;
            float g0 = par[256 + n0], g1 = par[257 + n0];
            float e0 = par[512 + n0], e1 = par[513 + n0];
            float y0 = fmaf((acc[mt][nt][0] - meanA) * rstdA, g0, e0);
            float y1 = fmaf((acc[mt][nt][1] - meanA) * rstdA, g1, e1);
            float y2 = fmaf((acc[mt][nt][2] - meanB) * rstdB, g0, e0);
            float y3 = fmaf((acc[mt][nt][3] - meanB) * rstdB, g1, e1);
            if (ACT) { y0 = elu1(y0); y1 = elu1(y1); y2 = elu1(y2); y3 = elu1(y3); }
            int aln = ((lane >> 2) << 2) + ((n0 & 7) >> 1);
            int rA  = ((n0 & 15) >= 8) ? 2 : 0;
            int idxb = ((mt * 16 + (n0 >> 4)) * 32 + aln) * 4 + rA;
            uint32_t hp, lp;
            split_pack(y0, y1, hp, lp);
            ah[idxb] = hp; al[idxb] = lp;            // row mA   (r bit0 = 0)
            split_pack(y2, y3, hp, lp);
            ah[idxb + 1] = hp; al[idxb + 1] = lp;    // row mA+8 (r bit0 = 1)
        }
    }
    __syncthreads();
}

__device__ __forceinline__ void final_layer(
    unsigned char* smem, const uint4* __restrict__ bfr,
    const float* __restrict__ bv, const float* __restrict__ gv, const float* __restrict__ bev,
    float* __restrict__ out, int r0, int p, int tid)
{
    const int lane = tid & 31, wid = tid >> 5;   // warp owns rows [wid*16, +16)
    uint32_t* ah = reinterpret_cast<uint32_t*>(smem + AFRAG_HI);
    uint32_t* al = reinterpret_cast<uint32_t*>(smem + AFRAG_LO);
    float* par = reinterpret_cast<float*>(smem + PAR_OFF);

    for (int i = tid; i < 96; i += 256)
        par[i] = (i < 32) ? bv[i] : (i < 64 ? gv[i - 32] : bev[i - 64]);

    float acc[4][4];
#pragma unroll
    for (int nt = 0; nt < 4; nt++)
#pragma unroll
        for (int r = 0; r < 4; r++) acc[nt][r] = 0.f;

#pragma unroll 1
    for (int kt = 0; kt < 16; kt++) {
        uint4 B[4];
#pragma unroll
        for (int nt = 0; nt < 4; nt++)
            B[nt] = __ldg(&bfr[((size_t)kt * 4 + nt) * 32 + lane]);
        uint4 Ah = reinterpret_cast<const uint4*>(ah)[(wid * 16 + kt) * 32 + lane];
        uint4 Al = reinterpret_cast<const uint4*>(al)[(wid * 16 + kt) * 32 + lane];
#pragma unroll
        for (int nt = 0; nt < 4; nt++) {
            mma16816(acc[nt], Ah, B[nt].x, B[nt].y);
            mma16816(acc[nt], Ah, B[nt].z, B[nt].w);
            mma16816(acc[nt], Al, B[nt].x, B[nt].y);
        }
    }
    __syncthreads();   // par visible to all

    float s1a = 0.f, s2a = 0.f, s1b = 0.f, s2b = 0.f;
#pragma unroll
    for (int nt = 0; nt < 4; nt++) {
        int n0 = nt * 8 + (lane & 3) * 2;
        float b0 = par[n0], b1 = par[n0 + 1];
        float y0 = acc[nt][0] + b0, y1 = acc[nt][1] + b1;
        float y2 = acc[nt][2] + b0, y3 = acc[nt][3] + b1;
        acc[nt][0] = y0; acc[nt][1] = y1; acc[nt][2] = y2; acc[nt][3] = y3;
        s1a += y0 + y1; s2a = fmaf(y0, y0, fmaf(y1, y1, s2a));
        s1b += y2 + y3; s2b = fmaf(y2, y2, fmaf(y3, y3, s2b));
    }
    s1a += __shfl_xor_sync(~0u, s1a, 1); s1a += __shfl_xor_sync(~0u, s1a, 2);
    s2a += __shfl_xor_sync(~0u, s2a, 1); s2a += __shfl_xor_sync(~0u, s2a, 2);
    s1b += __shfl_xor_sync(~0u, s1b, 1); s1b += __shfl_xor_sync(~0u, s1b, 2);
    s2b += __shfl_xor_sync(~0u, s2b, 1); s2b += __shfl_xor_sync(~0u, s2b, 2);
    const float meanA = s1a * (1.f / 32.f);
    const float rstdA = rsqrtf(fmaf(-meanA, meanA, s2a * (1.f / 32.f)) + EPSV);
    const float meanB = s1b * (1.f / 32.f);
    const float rstdB = rsqrtf(fmaf(-meanB, meanB, s2b * (1.f / 32.f)) + EPSV);

    const int mA = wid * 16 + (lane >> 2);
#pragma unroll
    for (int nt = 0; nt < 4; nt++) {
        int n0 = nt * 8 + (lane & 3) * 2;
        float g0 = par[32 + n0], g1 = par[33 + n0];
        float e0 = par[64 + n0], e1 = par[65 + n0];
        float2 o;
        o.x = fmaf((acc[nt][0] - meanA) * rstdA, g0, e0);
        o.y = fmaf((acc[nt][1] - meanA) * rstdA, g1, e1);
        *reinterpret_cast<float2*>(out + (size_t)(r0 + mA) * (NP * ACTD) + p * ACTD + n0) = o;
        o.x = fmaf((acc[nt][2] - meanB) * rstdB, g0, e0);
        o.y = fmaf((acc[nt][3] - meanB) * rstdB, g1, e1);
        *reinterpret_cast<float2*>(out + (size_t)(r0 + mA + 8) * (NP * ACTD) + p * ACTD + n0) = o;
    }
}

__global__ __launch_bounds__(256, 1)
void mlp_fused_kernel(
    const float* __restrict__ obs,
    const float* __restrict__ b1, const float* __restrict__ g1, const float* __restrict__ be1,
    const float* __restrict__ b2, const float* __restrict__ g2, const float* __restrict__ be2,
    const float* __restrict__ b3, const float* __restrict__ g3, const float* __restrict__ be3,
    const float* __restrict__ b4, const float* __restrict__ g4, const float* __restrict__ be4,
    float* __restrict__ out)
{
    extern __shared__ unsigned char smem[];
    const int tid = threadIdx.x;
    const int p   = blockIdx.y;
    const int r0  = blockIdx.x * MT;
    uint32_t* ah = reinterpret_cast<uint32_t*>(smem + AFRAG_HI);
    uint32_t* al = reinterpret_cast<uint32_t*>(smem + AFRAG_LO);

    // stage observation tile as split-bf16 A-fragments
    {
        const int m = tid >> 1, half = tid & 1;
        const float* orow = obs + (size_t)(r0 + m) * OBSD + half * 64;
#pragma unroll
        for (int j = 0; j < 32; j++) {
            float2 v = reinterpret_cast<const float2*>(orow)[j];
            uint32_t hp, lp; split_pack(v.x, v.y, hp, lp);
            int k = half * 64 + j * 2;
            int aln = ((m & 7) << 2) + ((k & 7) >> 1);
            int r = (((k & 15) >= 8) ? 2 : 0) + (((m & 15) >= 8) ? 1 : 0);
            int idx = (((m >> 4) * 16 + (k >> 4)) * 32 + aln) * 4 + r;
            ah[idx] = hp; al[idx] = lp;
        }
    }
    __syncthreads();

    hidden_layer<OBSD, true>(smem,
        reinterpret_cast<const uint4*>(g_wimg + OFF_L1 + (size_t)p * L1_BYTES),
        b1 + p * HIDD, g1 + p * HIDD, be1 + p * HIDD, tid);
    hidden_layer<HIDD, true>(smem,
        reinterpret_cast<const uint4*>(g_wimg + OFF_L2 + (size_t)p * L2_BYTES),
        b2 + p * HIDD, g2 + p * HIDD, be2 + p * HIDD, tid);
    hidden_layer<HIDD, true>(smem,
        reinterpret_cast<const uint4*>(g_wimg + OFF_L3 + (size_t)p * L2_BYTES),
        b3 + p * HIDD, g3 + p * HIDD, be3 + p * HIDD, tid);
    final_layer(smem,
        reinterpret_cast<const uint4*>(g_wimg + OFF_L4 + (size_t)p * L4_BYTES),
        b4 + p * ACTD, g4 + p * ACTD, be4 + p * ACTD, out, r0, p, tid);
}

// ---------------- launch ----------------
extern "C" void kernel_launch(void* const* d_in, const int* in_sizes, int n_in,
                              void* d_out, int out_size)
{
    const float* obs = (const float*)d_in[0];
    const float* W1  = (const float*)d_in[1];
    const float* b1  = (const float*)d_in[2];
    const float* g1  = (const float*)d_in[3];
    const float* be1 = (const float*)d_in[4];
    const float* W2  = (const float*)d_in[5];
    const float* b2  = (const float*)d_in[6];
    const float* g2  = (const float*)d_in[7];
    const float* be2 = (const float*)d_in[8];
    const float* W3  = (const float*)d_in[9];
    const float* b3  = (const float*)d_in[10];
    const float* g3  = (const float*)d_in[11];
    const float* be3 = (const float*)d_in[12];
    const float* W4  = (const float*)d_in[13];
    const float* b4  = (const float*)d_in[14];
    const float* g4  = (const float*)d_in[15];
    const float* be4 = (const float*)d_in[16];
    float* out = (float*)d_out;

    prep_kernel<HIDD, OBSD><<<dim3(NP, OBSD / 16), 256>>>(W1, OFF_L1);
    prep_kernel<HIDD, HIDD><<<dim3(NP, HIDD / 16), 256>>>(W2, OFF_L2);
    prep_kernel<HIDD, HIDD><<<dim3(NP, HIDD / 16), 256>>>(W3, OFF_L3);
    prep_kernel<ACTD, HIDD><<<dim3(NP, HIDD / 16), 256>>>(W4, OFF_L4);

    cudaFuncSetAttribute(mlp_fused_kernel,
                         cudaFuncAttributeMaxDynamicSharedMemorySize, DSMEM_BYTES);
    dim3 grid(NB / MT, NP);
    mlp_fused_kernel<<<grid, 256, DSMEM_BYTES>>>(
        obs, b1, g1, be1, b2, g2, be2, b3, g3, be3, b4, g4, be4, out);
}

// round 5
// speedup vs baseline: 4.3783x; 1.3869x over previous
#include <cuda_runtime.h>
#include <cuda_bf16.h>
#include <cstdint>

#define OBSD 128
#define ACTD 32
#define HIDD 256
#define NP   64
#define NB   4096
#define MT   128
#define EPSV 1e-5f

// ---------------- SMEM layout (bytes) ----------------
#define AFRAG_HI 0          // 8 mtiles x 16 ktiles x 32 lanes x 16B = 64KB
#define AFRAG_LO 65536
#define PAR_OFF  131072     // 768 floats (bias | gamma | beta)
#define RED1_OFF 134144     // 8*128 floats
#define RED2_OFF 138240     // 8*128 floats
#define DSMEM_BYTES 142336

// ---------------- weight fragment image ----------------
#define L1_BYTES ((size_t)OBSD*HIDD*4)   // per-policy bytes (hi+lo bf16 = 4B/elem)
#define L2_BYTES ((size_t)HIDD*HIDD*4)
#define L4_BYTES ((size_t)HIDD*ACTD*4)
#define OFF_L1 0ull
#define OFF_L2 (OFF_L1 + 64ull*L1_BYTES)
#define OFF_L3 (OFF_L2 + 64ull*L2_BYTES)
#define OFF_L4 (OFF_L3 + 64ull*L2_BYTES)
#define WIMG_TOTAL (OFF_L4 + 64ull*L4_BYTES)

__device__ __align__(128) unsigned char g_wimg[WIMG_TOTAL];

// ---------------- helpers ----------------
__device__ __forceinline__ void mma16816(float* c, const uint4& a, uint32_t b0, uint32_t b1) {
    asm volatile(
        "mma.sync.aligned.m16n8k16.row.col.f32.bf16.bf16.f32 "
        "{%0,%1,%2,%3}, {%4,%5,%6,%7}, {%8,%9}, {%0,%1,%2,%3};"
        : "+f"(c[0]), "+f"(c[1]), "+f"(c[2]), "+f"(c[3])
        : "r"(a.x), "r"(a.y), "r"(a.z), "r"(a.w), "r"(b0), "r"(b1));
}

__device__ __forceinline__ void split_pack(float y0, float y1, uint32_t& hp, uint32_t& lp) {
    __nv_bfloat16 h0 = __float2bfloat16_rn(y0);
    __nv_bfloat16 h1 = __float2bfloat16_rn(y1);
    __nv_bfloat16 l0 = __float2bfloat16_rn(y0 - __bfloat162float(h0));
    __nv_bfloat16 l1 = __float2bfloat16_rn(y1 - __bfloat162float(h1));
    hp = (uint32_t)__bfloat16_as_ushort(h0) | ((uint32_t)__bfloat16_as_ushort(h1) << 16);
    lp = (uint32_t)__bfloat16_as_ushort(l0) | ((uint32_t)__bfloat16_as_ushort(l1) << 16);
}

__device__ __forceinline__ float elu1(float y) { return y > 0.f ? y : expm1f(y); }

// ---------------- weight preprocess (unchanged from R3, validated) ----------------
template<int N, int K>
__global__ void prep_kernel(const float* __restrict__ W, size_t off)
{
    __shared__ float tile[16 * N];
    const int p = blockIdx.x, kt = blockIdx.y;
    const int tid = threadIdx.x;
    const float4* src = reinterpret_cast<const float4*>(W + ((size_t)p * K + (size_t)kt * 16) * N);
    constexpr int NL4 = 16 * N / 4;
    for (int i = tid; i < NL4; i += 256)
        reinterpret_cast<float4*>(tile)[i] = src[i];
    __syncthreads();
    constexpr int NT = N / 8;
    uint4* dst = reinterpret_cast<uint4*>(g_wimg + off + (size_t)p * ((size_t)K * N * 4));
    for (int u = tid; u < NT * 32; u += 256) {
        int nt = u >> 5, lane = u & 31;
        int n = nt * 8 + (lane >> 2), q = (lane & 3) * 2;
        uint32_t hp[2], lp[2];
#pragma unroll
        for (int r = 0; r < 2; r++) {
            float w0 = tile[(q + 8 * r) * N + n];
            float w1 = tile[(q + 8 * r + 1) * N + n];
            __nv_bfloat16 h0 = __float2bfloat16_rn(w0);
            __nv_bfloat16 h1 = __float2bfloat16_rn(w1);
            __nv_bfloat16 l0 = __float2bfloat16_rn(w0 - __bfloat162float(h0));
            __nv_bfloat16 l1 = __float2bfloat16_rn(w1 - __bfloat162float(h1));
            hp[r] = (uint32_t)__bfloat16_as_ushort(h0) | ((uint32_t)__bfloat16_as_ushort(h1) << 16);
            lp[r] = (uint32_t)__bfloat16_as_ushort(l0) | ((uint32_t)__bfloat16_as_ushort(l1) << 16);
        }
        uint4 v; v.x = hp[0]; v.y = hp[1]; v.z = lp[0]; v.w = lp[1];
        dst[((size_t)kt * NT + nt) * 32 + lane] = v;
    }
}

// ---------------- fused main kernel ----------------
// A-fragment smem layout (validated in R3): idx(m,k) -> uint32 slot
//   mtile=m/16, ktile=k/16, a_lane=(m%8)*4+((k%8)/2), r=2*((k%16)>=8)+((m%16)>=8)
//   idx = ((mtile*16 + ktile)*32 + a_lane)*4 + r
//
// 16 warps: wn = wid>>1 (8 col groups of 32), mg = wid&1 (2 row groups of 64).
// Warp computes mtiles [mg*4, mg*4+4) x ntiles [wn*4, wn*4+4).

template<int K, bool ACT>
__device__ __forceinline__ void hidden_layer(
    unsigned char* smem,
    const uint4* __restrict__ bfr,
    const float* __restrict__ bv, const float* __restrict__ gv, const float* __restrict__ bev,
    int tid)
{
    const int lane = tid & 31;
    const int wid  = tid >> 5;
    const int wn   = wid >> 1;
    const int mg   = wid & 1;
    uint32_t* ah = reinterpret_cast<uint32_t*>(smem + AFRAG_HI);
    uint32_t* al = reinterpret_cast<uint32_t*>(smem + AFRAG_LO);
    float* par  = reinterpret_cast<float*>(smem + PAR_OFF);
    float* red1 = reinterpret_cast<float*>(smem + RED1_OFF);
    float* red2 = reinterpret_cast<float*>(smem + RED2_OFF);

    for (int i = tid; i < 768; i += 512)
        par[i] = (i < 256) ? bv[i] : (i < 512 ? gv[i - 256] : bev[i - 512]);

    float acc[4][4][4];
#pragma unroll
    for (int q = 0; q < 4; q++)
#pragma unroll
        for (int nt = 0; nt < 4; nt++)
#pragma unroll
            for (int r = 0; r < 4; r++) acc[q][nt][r] = 0.f;

    const uint4* bwarp = bfr + (size_t)wn * 128 + lane;   // + kt*32*32 + nt*32
    constexpr int KTN = K / 16;
#pragma unroll 1
    for (int kt = 0; kt < KTN; kt++) {
        uint4 B[4];
#pragma unroll
        for (int nt = 0; nt < 4; nt++)
            B[nt] = __ldg(bwarp + (size_t)kt * 1024 + nt * 32);
#pragma unroll
        for (int q = 0; q < 4; q++) {
            const int mt = mg * 4 + q;
            uint4 Ah = reinterpret_cast<const uint4*>(ah)[(mt * 16 + kt) * 32 + lane];
            uint4 Al = reinterpret_cast<const uint4*>(al)[(mt * 16 + kt) * 32 + lane];
#pragma unroll
            for (int nt = 0; nt < 4; nt++) {
                mma16816(acc[q][nt], Ah, B[nt].x, B[nt].y);  // hi*hi
                mma16816(acc[q][nt], Ah, B[nt].z, B[nt].w);  // hi*lo
                mma16816(acc[q][nt], Al, B[nt].x, B[nt].y);  // lo*hi
            }
        }
    }
    __syncthreads();   // A reads done everywhere; par visible

    // bias + per-row partial sums (this warp's 32-col slice of its 64 rows)
#pragma unroll
    for (int q = 0; q < 4; q++) {
        const int mt = mg * 4 + q;
        float s1a = 0.f, s2a = 0.f, s1b = 0.f, s2b = 0.f;
#pragma unroll
        for (int nt = 0; nt < 4; nt++) {
            int n0 = wn * 32 + nt * 8 + (lane & 3) * 2;
            float b0 = par[n0], b1 = par[n0 + 1];
            float y0 = acc[q][nt][0] + b0, y1 = acc[q][nt][1] + b1;
            float y2 = acc[q][nt][2] + b0, y3 = acc[q][nt][3] + b1;
            acc[q][nt][0] = y0; acc[q][nt][1] = y1;
            acc[q][nt][2] = y2; acc[q][nt][3] = y3;
            s1a += y0 + y1; s2a = fmaf(y0, y0, fmaf(y1, y1, s2a));
            s1b += y2 + y3; s2b = fmaf(y2, y2, fmaf(y3, y3, s2b));
        }
        s1a += __shfl_xor_sync(~0u, s1a, 1); s1a += __shfl_xor_sync(~0u, s1a, 2);
        s2a += __shfl_xor_sync(~0u, s2a, 1); s2a += __shfl_xor_sync(~0u, s2a, 2);
        s1b += __shfl_xor_sync(~0u, s1b, 1); s1b += __shfl_xor_sync(~0u, s1b, 2);
        s2b += __shfl_xor_sync(~0u, s2b, 1); s2b += __shfl_xor_sync(~0u, s2b, 2);
        if ((lane & 3) == 0) {
            int m0 = mt * 16 + (lane >> 2);
            red1[wn * 128 + m0]     = s1a; red2[wn * 128 + m0]     = s2a;
            red1[wn * 128 + m0 + 8] = s1b; red2[wn * 128 + m0 + 8] = s2b;
        }
    }
    __syncthreads();
    if (tid < 128) {
        float t1 = 0.f, t2 = 0.f;
#pragma unroll
        for (int w = 0; w < 8; w++) { t1 += red1[w * 128 + tid]; t2 += red2[w * 128 + tid]; }
        float mean = t1 * (1.f / 256.f);
        float var  = fmaf(-mean, mean, t2 * (1.f / 256.f));
        float rstd = rsqrtf(var + EPSV);
        red1[tid] = mean; red2[tid] = rstd;
    }
    __syncthreads();

    // normalize + activation + write next layer's A-fragments
#pragma unroll
    for (int q = 0; q < 4; q++) {
        const int mt = mg * 4 + q;
        int mA = mt * 16 + (lane >> 2);
        float meanA = red1[mA],     rstdA = red2[mA];
        float meanB = red1[mA + 8], rstdB = red2[mA + 8];
#pragma unroll
        for (int nt = 0; nt < 4; nt++) {
            int n0 = wn * 32 + nt * 8 + (lane & 3) * 2;
            float g0 = par[256 + n0], g1 = par[257 + n0];
            float e0 = par[512 + n0], e1 = par[513 + n0];
            float y0 = fmaf((acc[q][nt][0] - meanA) * rstdA, g0, e0);
            float y1 = fmaf((acc[q][nt][1] - meanA) * rstdA, g1, e1);
            float y2 = fmaf((acc[q][nt][2] - meanB) * rstdB, g0, e0);
            float y3 = fmaf((acc[q][nt][3] - meanB) * rstdB, g1, e1);
            if (ACT) { y0 = elu1(y0); y1 = elu1(y1); y2 = elu1(y2); y3 = elu1(y3); }
            int aln = ((lane >> 2) << 2) + ((n0 & 7) >> 1);
            int rA  = ((n0 & 15) >= 8) ? 2 : 0;
            int idxb = ((mt * 16 + (n0 >> 4)) * 32 + aln) * 4 + rA;
            uint32_t hp, lp;
            split_pack(y0, y1, hp, lp);
            ah[idxb] = hp; al[idxb] = lp;            // row mA   (r bit0 = 0)
            split_pack(y2, y3, hp, lp);
            ah[idxb + 1] = hp; al[idxb + 1] = lp;    // row mA+8 (r bit0 = 1)
        }
    }
    __syncthreads();
}

__device__ __forceinline__ void final_layer(
    unsigned char* smem, const uint4* __restrict__ bfr,
    const float* __restrict__ bv, const float* __restrict__ gv, const float* __restrict__ bev,
    float* __restrict__ out, int r0, int p, int tid)
{
    const int lane = tid & 31, wid = tid >> 5;   // warps 0-7 own rows [wid*16, +16)
    uint32_t* ah = reinterpret_cast<uint32_t*>(smem + AFRAG_HI);
    uint32_t* al = reinterpret_cast<uint32_t*>(smem + AFRAG_LO);
    float* par = reinterpret_cast<float*>(smem + PAR_OFF);

    for (int i = tid; i < 96; i += 512)
        par[i] = (i < 32) ? bv[i] : (i < 64 ? gv[i - 32] : bev[i - 64]);

    float acc[4][4];
#pragma unroll
    for (int nt = 0; nt < 4; nt++)
#pragma unroll
        for (int r = 0; r < 4; r++) acc[nt][r] = 0.f;

    if (wid < 8) {
#pragma unroll 1
        for (int kt = 0; kt < 16; kt++) {
            uint4 B[4];
#pragma unroll
            for (int nt = 0; nt < 4; nt++)
                B[nt] = __ldg(&bfr[((size_t)kt * 4 + nt) * 32 + lane]);
            uint4 Ah = reinterpret_cast<const uint4*>(ah)[(wid * 16 + kt) * 32 + lane];
            uint4 Al = reinterpret_cast<const uint4*>(al)[(wid * 16 + kt) * 32 + lane];
#pragma unroll
            for (int nt = 0; nt < 4; nt++) {
                mma16816(acc[nt], Ah, B[nt].x, B[nt].y);
                mma16816(acc[nt], Ah, B[nt].z, B[nt].w);
                mma16816(acc[nt], Al, B[nt].x, B[nt].y);
            }
        }
    }
    __syncthreads();   // par visible to all
    if (wid >= 8) return;

    float s1a = 0.f, s2a = 0.f, s1b = 0.f, s2b = 0.f;
#pragma unroll
    for (int nt = 0; nt < 4; nt++) {
        int n0 = nt * 8 + (lane & 3) * 2;
        float b0 = par[n0], b1 = par[n0 + 1];
        float y0 = acc[nt][0] + b0, y1 = acc[nt][1] + b1;
        float y2 = acc[nt][2] + b0, y3 = acc[nt][3] + b1;
        acc[nt][0] = y0; acc[nt][1] = y1; acc[nt][2] = y2; acc[nt][3] = y3;
        s1a += y0 + y1; s2a = fmaf(y0, y0, fmaf(y1, y1, s2a));
        s1b += y2 + y3; s2b = fmaf(y2, y2, fmaf(y3, y3, s2b));
    }
    s1a += __shfl_xor_sync(~0u, s1a, 1); s1a += __shfl_xor_sync(~0u, s1a, 2);
    s2a += __shfl_xor_sync(~0u, s2a, 1); s2a += __shfl_xor_sync(~0u, s2a, 2);
    s1b += __shfl_xor_sync(~0u, s1b, 1); s1b += __shfl_xor_sync(~0u, s1b, 2);
    s2b += __shfl_xor_sync(~0u, s2b, 1); s2b += __shfl_xor_sync(~0u, s2b, 2);
    const float meanA = s1a * (1.f / 32.f);
    const float rstdA = rsqrtf(fmaf(-meanA, meanA, s2a * (1.f / 32.f)) + EPSV);
    const float meanB = s1b * (1.f / 32.f);
    const float rstdB = rsqrtf(fmaf(-meanB, meanB, s2b * (1.f / 32.f)) + EPSV);

    const int mA = wid * 16 + (lane >> 2);
#pragma unroll
    for (int nt = 0; nt < 4; nt++) {
        int n0 = nt * 8 + (lane & 3) * 2;
        float g0 = par[32 + n0], g1 = par[33 + n0];
        float e0 = par[64 + n0], e1 = par[65 + n0];
        float2 o;
        o.x = fmaf((acc[nt][0] - meanA) * rstdA, g0, e0);
        o.y = fmaf((acc[nt][1] - meanA) * rstdA, g1, e1);
        *reinterpret_cast<float2*>(out + (size_t)(r0 + mA) * (NP * ACTD) + p * ACTD + n0) = o;
        o.x = fmaf((acc[nt][2] - meanB) * rstdB, g0, e0);
        o.y = fmaf((acc[nt][3] - meanB) * rstdB, g1, e1);
        *reinterpret_cast<float2*>(out + (size_t)(r0 + mA + 8) * (NP * ACTD) + p * ACTD + n0) = o;
    }
}

__global__ __launch_bounds__(512, 1)
void mlp_fused_kernel(
    const float* __restrict__ obs,
    const float* __restrict__ b1, const float* __restrict__ g1, const float* __restrict__ be1,
    const float* __restrict__ b2, const float* __restrict__ g2, const float* __restrict__ be2,
    const float* __restrict__ b3, const float* __restrict__ g3, const float* __restrict__ be3,
    const float* __restrict__ b4, const float* __restrict__ g4, const float* __restrict__ be4,
    float* __restrict__ out)
{
    extern __shared__ unsigned char smem[];
    const int tid = threadIdx.x;
    const int p   = blockIdx.y;
    const int r0  = blockIdx.x * MT;
    uint32_t* ah = reinterpret_cast<uint32_t*>(smem + AFRAG_HI);
    uint32_t* al = reinterpret_cast<uint32_t*>(smem + AFRAG_LO);

    // stage observation tile as split-bf16 A-fragments (512 threads, 32 floats each)
    {
        const int m = tid >> 2, q4 = tid & 3;
        const float* orow = obs + (size_t)(r0 + m) * OBSD + q4 * 32;
#pragma unroll
        for (int j = 0; j < 16; j++) {
            float2 v = reinterpret_cast<const float2*>(orow)[j];
            uint32_t hp, lp; split_pack(v.x, v.y, hp, lp);
            int k = q4 * 32 + j * 2;
            int aln = ((m & 7) << 2) + ((k & 7) >> 1);
            int r = (((k & 15) >= 8) ? 2 : 0) + (((m & 15) >= 8) ? 1 : 0);
            int idx = (((m >> 4) * 16 + (k >> 4)) * 32 + aln) * 4 + r;
            ah[idx] = hp; al[idx] = lp;
        }
    }
    __syncthreads();

    hidden_layer<OBSD, true>(smem,
        reinterpret_cast<const uint4*>(g_wimg + OFF_L1 + (size_t)p * L1_BYTES),
        b1 + p * HIDD, g1 + p * HIDD, be1 + p * HIDD, tid);
    hidden_layer<HIDD, true>(smem,
        reinterpret_cast<const uint4*>(g_wimg + OFF_L2 + (size_t)p * L2_BYTES),
        b2 + p * HIDD, g2 + p * HIDD, be2 + p * HIDD, tid);
    hidden_layer<HIDD, true>(smem,
        reinterpret_cast<const uint4*>(g_wimg + OFF_L3 + (size_t)p * L2_BYTES),
        b3 + p * HIDD, g3 + p * HIDD, be3 + p * HIDD, tid);
    final_layer(smem,
        reinterpret_cast<const uint4*>(g_wimg + OFF_L4 + (size_t)p * L4_BYTES),
        b4 + p * ACTD, g4 + p * ACTD, be4 + p * ACTD, out, r0, p, tid);
}

// ---------------- launch ----------------
extern "C" void kernel_launch(void* const* d_in, const int* in_sizes, int n_in,
                              void* d_out, int out_size)
{
    const float* obs = (const float*)d_in[0];
    const float* W1  = (const float*)d_in[1];
    const float* b1  = (const float*)d_in[2];
    const float* g1  = (const float*)d_in[3];
    const float* be1 = (const float*)d_in[4];
    const float* W2  = (const float*)d_in[5];
    const float* b2  = (const float*)d_in[6];
    const float* g2  = (const float*)d_in[7];
    const float* be2 = (const float*)d_in[8];
    const float* W3  = (const float*)d_in[9];
    const float* b3  = (const float*)d_in[10];
    const float* g3  = (const float*)d_in[11];
    const float* be3 = (const float*)d_in[12];
    const float* W4  = (const float*)d_in[13];
    const float* b4  = (const float*)d_in[14];
    const float* g4  = (const float*)d_in[15];
    const float* be4 = (const float*)d_in[16];
    float* out = (float*)d_out;

    prep_kernel<HIDD, OBSD><<<dim3(NP, OBSD / 16), 256>>>(W1, OFF_L1);
    prep_kernel<HIDD, HIDD><<<dim3(NP, HIDD / 16), 256>>>(W2, OFF_L2);
    prep_kernel<HIDD, HIDD><<<dim3(NP, HIDD / 16), 256>>>(W3, OFF_L3);
    prep_kernel<ACTD, HIDD><<<dim3(NP, HIDD / 16), 256>>>(W4, OFF_L4);

    cudaFuncSetAttribute(mlp_fused_kernel,
                         cudaFuncAttributeMaxDynamicSharedMemorySize, DSMEM_BYTES);
    dim3 grid(NB / MT, NP);
    mlp_fused_kernel<<<grid, 512, DSMEM_BYTES>>>(
        obs, b1, g1, be1, b2, g2, be2, b3, g3, be3, b4, g4, be4, out);
}

// round 6
// speedup vs baseline: 5.1133x; 1.1679x over previous
#include <cuda_runtime.h>
#include <cuda_bf16.h>
#include <cstdint>

#define OBSD 128
#define ACTD 32
#define HIDD 256
#define NP   64
#define NB   4096
#define MT   64
#define EPSV 1e-5f

// ---------------- SMEM layout (bytes) ----------------
#define AFRAG_HI 0          // 4 mtiles x 16 ktiles x 32 lanes x 16B = 32KB
#define AFRAG_LO 32768
#define PAR_OFF  65536      // 768 floats (bias | gamma | beta)
#define RED1_OFF 68608      // 8*64 floats
#define RED2_OFF 70656      // 8*64 floats
#define DSMEM_BYTES 72704

// ---------------- weight fragment image ----------------
#define L1_BYTES ((size_t)OBSD*HIDD*4)   // per-policy bytes (hi+lo bf16 = 4B/elem)
#define L2_BYTES ((size_t)HIDD*HIDD*4)
#define L4_BYTES ((size_t)HIDD*ACTD*4)
#define OFF_L1 0ull
#define OFF_L2 (OFF_L1 + 64ull*L1_BYTES)
#define OFF_L3 (OFF_L2 + 64ull*L2_BYTES)
#define OFF_L4 (OFF_L3 + 64ull*L2_BYTES)
#define WIMG_TOTAL (OFF_L4 + 64ull*L4_BYTES)

__device__ __align__(128) unsigned char g_wimg[WIMG_TOTAL];

// ---------------- helpers ----------------
__device__ __forceinline__ void mma16816(float* c, const uint4& a, uint32_t b0, uint32_t b1) {
    asm volatile(
        "mma.sync.aligned.m16n8k16.row.col.f32.bf16.bf16.f32 "
        "{%0,%1,%2,%3}, {%4,%5,%6,%7}, {%8,%9}, {%0,%1,%2,%3};"
        : "+f"(c[0]), "+f"(c[1]), "+f"(c[2]), "+f"(c[3])
        : "r"(a.x), "r"(a.y), "r"(a.z), "r"(a.w), "r"(b0), "r"(b1));
}

__device__ __forceinline__ void split_pack(float y0, float y1, uint32_t& hp, uint32_t& lp) {
    __nv_bfloat16 h0 = __float2bfloat16_rn(y0);
    __nv_bfloat16 h1 = __float2bfloat16_rn(y1);
    __nv_bfloat16 l0 = __float2bfloat16_rn(y0 - __bfloat162float(h0));
    __nv_bfloat16 l1 = __float2bfloat16_rn(y1 - __bfloat162float(h1));
    hp = (uint32_t)__bfloat16_as_ushort(h0) | ((uint32_t)__bfloat16_as_ushort(h1) << 16);
    lp = (uint32_t)__bfloat16_as_ushort(l0) | ((uint32_t)__bfloat16_as_ushort(l1) << 16);
}

__device__ __forceinline__ float elu1(float y) { return y > 0.f ? y : expm1f(y); }

// ---------------- weight preprocess (unchanged, validated) ----------------
template<int N, int K>
__global__ void prep_kernel(const float* __restrict__ W, size_t off)
{
    __shared__ float tile[16 * N];
    const int p = blockIdx.x, kt = blockIdx.y;
    const int tid = threadIdx.x;
    const float4* src = reinterpret_cast<const float4*>(W + ((size_t)p * K + (size_t)kt * 16) * N);
    constexpr int NL4 = 16 * N / 4;
    for (int i = tid; i < NL4; i += 256)
        reinterpret_cast<float4*>(tile)[i] = src[i];
    __syncthreads();
    constexpr int NT = N / 8;
    uint4* dst = reinterpret_cast<uint4*>(g_wimg + off + (size_t)p * ((size_t)K * N * 4));
    for (int u = tid; u < NT * 32; u += 256) {
        int nt = u >> 5, lane = u & 31;
        int n = nt * 8 + (lane >> 2), q = (lane & 3) * 2;
        uint32_t hp[2], lp[2];
#pragma unroll
        for (int r = 0; r < 2; r++) {
            float w0 = tile[(q + 8 * r) * N + n];
            float w1 = tile[(q + 8 * r + 1) * N + n];
            __nv_bfloat16 h0 = __float2bfloat16_rn(w0);
            __nv_bfloat16 h1 = __float2bfloat16_rn(w1);
            __nv_bfloat16 l0 = __float2bfloat16_rn(w0 - __bfloat162float(h0));
            __nv_bfloat16 l1 = __float2bfloat16_rn(w1 - __bfloat162float(h1));
            hp[r] = (uint32_t)__bfloat16_as_ushort(h0) | ((uint32_t)__bfloat16_as_ushort(h1) << 16);
            lp[r] = (uint32_t)__bfloat16_as_ushort(l0) | ((uint32_t)__bfloat16_as_ushort(l1) << 16);
        }
        uint4 v; v.x = hp[0]; v.y = hp[1]; v.z = lp[0]; v.w = lp[1];
        dst[((size_t)kt * NT + nt) * 32 + lane] = v;
    }
}

// ---------------- fused main kernel ----------------
// A-fragment smem layout: idx(m,k) -> uint32 slot (m in [0,64))
//   mtile=m/16, ktile=k/16, a_lane=(m%8)*4+((k%8)/2), r=2*((k%16)>=8)+((m%16)>=8)
//   idx = ((mtile*16 + ktile)*32 + a_lane)*4 + r
//
// 8 warps: warp wn owns cols [wn*32, wn*32+32), computes all 4 mtiles (64 rows).

template<int K, bool ACT>
__device__ __forceinline__ void hidden_layer(
    unsigned char* smem,
    const uint4* __restrict__ bfr,
    const float* __restrict__ bv, const float* __restrict__ gv, const float* __restrict__ bev,
    int tid)
{
    const int lane = tid & 31;
    const int wn   = tid >> 5;
    uint32_t* ah = reinterpret_cast<uint32_t*>(smem + AFRAG_HI);
    uint32_t* al = reinterpret_cast<uint32_t*>(smem + AFRAG_LO);
    float* par  = reinterpret_cast<float*>(smem + PAR_OFF);
    float* red1 = reinterpret_cast<float*>(smem + RED1_OFF);
    float* red2 = reinterpret_cast<float*>(smem + RED2_OFF);

    for (int i = tid; i < 768; i += 256)
        par[i] = (i < 256) ? bv[i] : (i < 512 ? gv[i - 256] : bev[i - 512]);

    float acc[4][4][4];
#pragma unroll
    for (int q = 0; q < 4; q++)
#pragma unroll
        for (int nt = 0; nt < 4; nt++)
#pragma unroll
            for (int r = 0; r < 4; r++) acc[q][nt][r] = 0.f;

    const uint4* bwarp = bfr + (size_t)wn * 128 + lane;   // + kt*1024 + nt*32
    constexpr int KTN = K / 16;

    uint4 B[4];
#pragma unroll
    for (int nt = 0; nt < 4; nt++)
        B[nt] = __ldg(bwarp + nt * 32);

#pragma unroll 1
    for (int kt = 0; kt < KTN; kt++) {
        uint4 Bn[4];
        if (kt + 1 < KTN) {
#pragma unroll
            for (int nt = 0; nt < 4; nt++)
                Bn[nt] = __ldg(bwarp + (size_t)(kt + 1) * 1024 + nt * 32);
        }
#pragma unroll
        for (int q = 0; q < 4; q++) {
            uint4 Ah = reinterpret_cast<const uint4*>(ah)[(q * 16 + kt) * 32 + lane];
            uint4 Al = reinterpret_cast<const uint4*>(al)[(q * 16 + kt) * 32 + lane];
#pragma unroll
            for (int nt = 0; nt < 4; nt++) {
                mma16816(acc[q][nt], Ah, B[nt].x, B[nt].y);  // hi*hi
                mma16816(acc[q][nt], Ah, B[nt].z, B[nt].w);  // hi*lo
                mma16816(acc[q][nt], Al, B[nt].x, B[nt].y);  // lo*hi
            }
        }
#pragma unroll
        for (int nt = 0; nt < 4; nt++) B[nt] = Bn[nt];
    }
    __syncthreads();   // A reads done everywhere; par visible

    // bias + per-row partial sums (this warp's 32-col slice of all 64 rows)
#pragma unroll
    for (int q = 0; q < 4; q++) {
        float s1a = 0.f, s2a = 0.f, s1b = 0.f, s2b = 0.f;
#pragma unroll
        for (int nt = 0; nt < 4; nt++) {
            int n0 = wn * 32 + nt * 8 + (lane & 3) * 2;
            float b0 = par[n0], b1 = par[n0 + 1];
            float y0 = acc[q][nt][0] + b0, y1 = acc[q][nt][1] + b1;
            float y2 = acc[q][nt][2] + b0, y3 = acc[q][nt][3] + b1;
            acc[q][nt][0] = y0; acc[q][nt][1] = y1;
            acc[q][nt][2] = y2; acc[q][nt][3] = y3;
            s1a += y0 + y1; s2a = fmaf(y0, y0, fmaf(y1, y1, s2a));
            s1b += y2 + y3; s2b = fmaf(y2, y2, fmaf(y3, y3, s2b));
        }
        s1a += __shfl_xor_sync(~0u, s1a, 1); s1a += __shfl_xor_sync(~0u, s1a, 2);
        s2a += __shfl_xor_sync(~0u, s2a, 1); s2a += __shfl_xor_sync(~0u, s2a, 2);
        s1b += __shfl_xor_sync(~0u, s1b, 1); s1b += __shfl_xor_sync(~0u, s1b, 2);
        s2b += __shfl_xor_sync(~0u, s2b, 1); s2b += __shfl_xor_sync(~0u, s2b, 2);
        if ((lane & 3) == 0) {
            int m0 = q * 16 + (lane >> 2);
            red1[wn * 64 + m0]     = s1a; red2[wn * 64 + m0]     = s2a;
            red1[wn * 64 + m0 + 8] = s1b; red2[wn * 64 + m0 + 8] = s2b;
        }
    }
    __syncthreads();
    if (tid < 64) {
        float t1 = 0.f, t2 = 0.f;
#pragma unroll
        for (int w = 0; w < 8; w++) { t1 += red1[w * 64 + tid]; t2 += red2[w * 64 + tid]; }
        float mean = t1 * (1.f / 256.f);
        float var  = fmaf(-mean, mean, t2 * (1.f / 256.f));
        float rstd = rsqrtf(var + EPSV);
        red1[tid] = mean; red2[tid] = rstd;
    }
    __syncthreads();

    // normalize + activation + write next layer's A-fragments
#pragma unroll
    for (int q = 0; q < 4; q++) {
        int mA = q * 16 + (lane >> 2);
        float meanA = red1[mA],     rstdA = red2[mA];
        float meanB = red1[mA + 8], rstdB = red2[mA + 8];
#pragma unroll
        for (int nt = 0; nt < 4; nt++) {
            int n0 = wn * 32 + nt * 8 + (lane & 3) * 2;
            float g0 = par[256 + n0], g1 = par[257 + n0];
            float e0 = par[512 + n0], e1 = par[513 + n0];
            float y0 = fmaf((acc[q][nt][0] - meanA) * rstdA, g0, e0);
            float y1 = fmaf((acc[q][nt][1] - meanA) * rstdA, g1, e1);
            float y2 = fmaf((acc[q][nt][2] - meanB) * rstdB, g0, e0);
            float y3 = fmaf((acc[q][nt][3] - meanB) * rstdB, g1, e1);
            if (ACT) { y0 = elu1(y0); y1 = elu1(y1); y2 = elu1(y2); y3 = elu1(y3); }
            int aln = ((lane >> 2) << 2) + ((n0 & 7) >> 1);
            int rA  = ((n0 & 15) >= 8) ? 2 : 0;
            int idxb = ((q * 16 + (n0 >> 4)) * 32 + aln) * 4 + rA;
            uint32_t hp, lp;
            split_pack(y0, y1, hp, lp);
            ah[idxb] = hp; al[idxb] = lp;            // row mA   (r bit0 = 0)
            split_pack(y2, y3, hp, lp);
            ah[idxb + 1] = hp; al[idxb + 1] = lp;    // row mA+8 (r bit0 = 1)
        }
    }
    __syncthreads();
}

__device__ __forceinline__ void final_layer(
    unsigned char* smem, const uint4* __restrict__ bfr,
    const float* __restrict__ bv, const float* __restrict__ gv, const float* __restrict__ bev,
    float* __restrict__ out, int r0, int p, int tid)
{
    const int lane = tid & 31, wid = tid >> 5;   // warps 0-3 own rows [wid*16, +16)
    uint32_t* ah = reinterpret_cast<uint32_t*>(smem + AFRAG_HI);
    uint32_t* al = reinterpret_cast<uint32_t*>(smem + AFRAG_LO);
    float* par = reinterpret_cast<float*>(smem + PAR_OFF);

    for (int i = tid; i < 96; i += 256)
        par[i] = (i < 32) ? bv[i] : (i < 64 ? gv[i - 32] : bev[i - 64]);

    float acc[4][4];
#pragma unroll
    for (int nt = 0; nt < 4; nt++)
#pragma unroll
        for (int r = 0; r < 4; r++) acc[nt][r] = 0.f;

    if (wid < 4) {
#pragma unroll 1
        for (int kt = 0; kt < 16; kt++) {
            uint4 B[4];
#pragma unroll
            for (int nt = 0; nt < 4; nt++)
                B[nt] = __ldg(&bfr[((size_t)kt * 4 + nt) * 32 + lane]);
            uint4 Ah = reinterpret_cast<const uint4*>(ah)[(wid * 16 + kt) * 32 + lane];
            uint4 Al = reinterpret_cast<const uint4*>(al)[(wid * 16 + kt) * 32 + lane];
#pragma unroll
            for (int nt = 0; nt < 4; nt++) {
                mma16816(acc[nt], Ah, B[nt].x, B[nt].y);
                mma16816(acc[nt], Ah, B[nt].z, B[nt].w);
                mma16816(acc[nt], Al, B[nt].x, B[nt].y);
            }
        }
    }
    __syncthreads();   // par visible to all
    if (wid >= 4) return;

    float s1a = 0.f, s2a = 0.f, s1b = 0.f, s2b = 0.f;
#pragma unroll
    for (int nt = 0; nt < 4; nt++) {
        int n0 = nt * 8 + (lane & 3) * 2;
        float b0 = par[n0], b1 = par[n0 + 1];
        float y0 = acc[nt][0] + b0, y1 = acc[nt][1] + b1;
        float y2 = acc[nt][2] + b0, y3 = acc[nt][3] + b1;
        acc[nt][0] = y0; acc[nt][1] = y1; acc[nt][2] = y2; acc[nt][3] = y3;
        s1a += y0 + y1; s2a = fmaf(y0, y0, fmaf(y1, y1, s2a));
        s1b += y2 + y3; s2b = fmaf(y2, y2, fmaf(y3, y3, s2b));
    }
    s1a += __shfl_xor_sync(~0u, s1a, 1); s1a += __shfl_xor_sync(~0u, s1a, 2);
    s2a += __shfl_xor_sync(~0u, s2a, 1); s2a += __shfl_xor_sync(~0u, s2a, 2);
    s1b += __shfl_xor_sync(~0u, s1b, 1); s1b += __shfl_xor_sync(~0u, s1b, 2);
    s2b += __shfl_xor_sync(~0u, s2b, 1); s2b += __shfl_xor_sync(~0u, s2b, 2);
    const float meanA = s1a * (1.f / 32.f);
    const float rstdA = rsqrtf(fmaf(-meanA, meanA, s2a * (1.f / 32.f)) + EPSV);
    const float meanB = s1b * (1.f / 32.f);
    const float rstdB = rsqrtf(fmaf(-meanB, meanB, s2b * (1.f / 32.f)) + EPSV);

    const int mA = wid * 16 + (lane >> 2);
#pragma unroll
    for (int nt = 0; nt < 4; nt++) {
        int n0 = nt * 8 + (lane & 3) * 2;
        float g0 = par[32 + n0], g1 = par[33 + n0];
        float e0 = par[64 + n0], e1 = par[65 + n0];
        float2 o;
        o.x = fmaf((acc[nt][0] - meanA) * rstdA, g0, e0);
        o.y = fmaf((acc[nt][1] - meanA) * rstdA, g1, e1);
        *reinterpret_cast<float2*>(out + (size_t)(r0 + mA) * (NP * ACTD) + p * ACTD + n0) = o;
        o.x = fmaf((acc[nt][2] - meanB) * rstdB, g0, e0);
        o.y = fmaf((acc[nt][3] - meanB) * rstdB, g1, e1);
        *reinterpret_cast<float2*>(out + (size_t)(r0 + mA + 8) * (NP * ACTD) + p * ACTD + n0) = o;
    }
}

__global__ __launch_bounds__(256, 2)
void mlp_fused_kernel(
    const float* __restrict__ obs,
    const float* __restrict__ b1, const float* __restrict__ g1, const float* __restrict__ be1,
    const float* __restrict__ b2, const float* __restrict__ g2, const float* __restrict__ be2,
    const float* __restrict__ b3, const float* __restrict__ g3, const float* __restrict__ be3,
    const float* __restrict__ b4, const float* __restrict__ g4, const float* __restrict__ be4,
    float* __restrict__ out)
{
    extern __shared__ unsigned char smem[];
    const int tid = threadIdx.x;
    const int p   = blockIdx.y;
    const int r0  = blockIdx.x * MT;
    uint32_t* ah = reinterpret_cast<uint32_t*>(smem + AFRAG_HI);
    uint32_t* al = reinterpret_cast<uint32_t*>(smem + AFRAG_LO);

    // stage observation tile as split-bf16 A-fragments (256 threads, 64 rows)
    {
        const int m = tid >> 2, q4 = tid & 3;
        const float* orow = obs + (size_t)(r0 + m) * OBSD + q4 * 32;
#pragma unroll
        for (int j = 0; j < 16; j++) {
            float2 v = reinterpret_cast<const float2*>(orow)[j];
            uint32_t hp, lp; split_pack(v.x, v.y, hp, lp);
            int k = q4 * 32 + j * 2;
            int aln = ((m & 7) << 2) + ((k & 7) >> 1);
            int r = (((k & 15) >= 8) ? 2 : 0) + (((m & 15) >= 8) ? 1 : 0);
            int idx = (((m >> 4) * 16 + (k >> 4)) * 32 + aln) * 4 + r;
            ah[idx] = hp; al[idx] = lp;
        }
    }
    __syncthreads();

    hidden_layer<OBSD, true>(smem,
        reinterpret_cast<const uint4*>(g_wimg + OFF_L1 + (size_t)p * L1_BYTES),
        b1 + p * HIDD, g1 + p * HIDD, be1 + p * HIDD, tid);
    hidden_layer<HIDD, true>(smem,
        reinterpret_cast<const uint4*>(g_wimg + OFF_L2 + (size_t)p * L2_BYTES),
        b2 + p * HIDD, g2 + p * HIDD, be2 + p * HIDD, tid);
    hidden_layer<HIDD, true>(smem,
        reinterpret_cast<const uint4*>(g_wimg + OFF_L3 + (size_t)p * L2_BYTES),
        b3 + p * HIDD, g3 + p * HIDD, be3 + p * HIDD, tid);
    final_layer(smem,
        reinterpret_cast<const uint4*>(g_wimg + OFF_L4 + (size_t)p * L4_BYTES),
        b4 + p * ACTD, g4 + p * ACTD, be4 + p * ACTD, out, r0, p, tid);
}

// ---------------- launch ----------------
extern "C" void kernel_launch(void* const* d_in, const int* in_sizes, int n_in,
                              void* d_out, int out_size)
{
    const float* obs = (const float*)d_in[0];
    const float* W1  = (const float*)d_in[1];
    const float* b1  = (const float*)d_in[2];
    const float* g1  = (const float*)d_in[3];
    const float* be1 = (const float*)d_in[4];
    const float* W2  = (const float*)d_in[5];
    const float* b2  = (const float*)d_in[6];
    const float* g2  = (const float*)d_in[7];
    const float* be2 = (const float*)d_in[8];
    const float* W3  = (const float*)d_in[9];
    const float* b3  = (const float*)d_in[10];
    const float* g3  = (const float*)d_in[11];
    const float* be3 = (const float*)d_in[12];
    const float* W4  = (const float*)d_in[13];
    const float* b4  = (const float*)d_in[14];
    const float* g4  = (const float*)d_in[15];
    const float* be4 = (const float*)d_in[16];
    float* out = (float*)d_out;

    prep_kernel<HIDD, OBSD><<<dim3(NP, OBSD / 16), 256>>>(W1, OFF_L1);
    prep_kernel<HIDD, HIDD><<<dim3(NP, HIDD / 16), 256>>>(W2, OFF_L2);
    prep_kernel<HIDD, HIDD><<<dim3(NP, HIDD / 16), 256>>>(W3, OFF_L3);
    prep_kernel<ACTD, HIDD><<<dim3(NP, HIDD / 16), 256>>>(W4, OFF_L4);

    cudaFuncSetAttribute(mlp_fused_kernel,
                         cudaFuncAttributeMaxDynamicSharedMemorySize, DSMEM_BYTES);
    dim3 grid(NB / MT, NP);
    mlp_fused_kernel<<<grid, 256, DSMEM_BYTES>>>(
        obs, b1, g1, be1, b2, g2, be2, b3, g3, be3, b4, g4, be4, out);
}

// round 7
// speedup vs baseline: 6.6431x; 1.2992x over previous
#include <cuda_runtime.h>
#include <cuda_bf16.h>
#include <cstdint>

#define OBSD 128
#define ACTD 32
#define HIDD 256
#define NP   64
#define NB   4096
#define MT   64
#define EPSV 1e-5f

// ---------------- SMEM layout (bytes) ----------------
#define AFRAG_HI 0          // 4 mtiles x 16 ktiles x 32 lanes x 16B = 32KB
#define AFRAG_LO 32768
#define PAR_OFF  65536      // 768 floats (bias | gamma | beta)
#define RED1_OFF 68608      // 8*64 floats
#define RED2_OFF 70656      // 8*64 floats
#define DSMEM_BYTES 72704

// ---------------- weight fragment image ----------------
#define L1_BYTES ((size_t)OBSD*HIDD*4)   // per-policy bytes (hi+lo bf16 = 4B/elem)
#define L2_BYTES ((size_t)HIDD*HIDD*4)
#define L4_BYTES ((size_t)HIDD*ACTD*4)
#define OFF_L1 0ull
#define OFF_L2 (OFF_L1 + 64ull*L1_BYTES)
#define OFF_L3 (OFF_L2 + 64ull*L2_BYTES)
#define OFF_L4 (OFF_L3 + 64ull*L2_BYTES)
#define WIMG_TOTAL (OFF_L4 + 64ull*L4_BYTES)

__device__ __align__(128) unsigned char g_wimg[WIMG_TOTAL];

// ---------------- helpers ----------------
__device__ __forceinline__ void mma16816(float* c, const uint4& a, uint32_t b0, uint32_t b1) {
    asm volatile(
        "mma.sync.aligned.m16n8k16.row.col.f32.bf16.bf16.f32 "
        "{%0,%1,%2,%3}, {%4,%5,%6,%7}, {%8,%9}, {%0,%1,%2,%3};"
        : "+f"(c[0]), "+f"(c[1]), "+f"(c[2]), "+f"(c[3])
        : "r"(a.x), "r"(a.y), "r"(a.z), "r"(a.w), "r"(b0), "r"(b1));
}

// packed split: hp = bf16x2{lo=y0, hi=y1}; lp = residuals, same order
__device__ __forceinline__ void split_pack(float y0, float y1, uint32_t& hp, uint32_t& lp) {
    asm("cvt.rn.bf16x2.f32 %0, %2, %1;" : "=r"(hp) : "f"(y0), "f"(y1));
    float f0 = __uint_as_float(hp << 16);
    float f1 = __uint_as_float(hp & 0xffff0000u);
    float r0 = y0 - f0, r1 = y1 - f1;
    asm("cvt.rn.bf16x2.f32 %0, %2, %1;" : "=r"(lp) : "f"(r0), "f"(r1));
}

__device__ __forceinline__ float elu1(float y) { return y > 0.f ? y : (__expf(y) - 1.f); }

// ---------------- weight preprocess (merged: one kernel, z = layer) ----------------
template<int N, int K>
__device__ __forceinline__ void prep_dev(const float* __restrict__ W, size_t off, float* tile)
{
    const int p = blockIdx.x, kt = blockIdx.y;
    if (kt >= K / 16) return;                    // uniform per block
    const int tid = threadIdx.x;
    const float4* src = reinterpret_cast<const float4*>(W + ((size_t)p * K + (size_t)kt * 16) * N);
    constexpr int NL4 = 16 * N / 4;
    for (int i = tid; i < NL4; i += 256)
        reinterpret_cast<float4*>(tile)[i] = src[i];
    __syncthreads();
    constexpr int NT = N / 8;
    uint4* dst = reinterpret_cast<uint4*>(g_wimg + off + (size_t)p * ((size_t)K * N * 4));
    for (int u = tid; u < NT * 32; u += 256) {
        int nt = u >> 5, lane = u & 31;
        int n = nt * 8 + (lane >> 2), q = (lane & 3) * 2;
        uint32_t hp[2], lp[2];
#pragma unroll
        for (int r = 0; r < 2; r++) {
            float w0 = tile[(q + 8 * r) * N + n];
            float w1 = tile[(q + 8 * r + 1) * N + n];
            split_pack(w0, w1, hp[r], lp[r]);
        }
        uint4 v; v.x = hp[0]; v.y = hp[1]; v.z = lp[0]; v.w = lp[1];
        dst[((size_t)kt * NT + nt) * 32 + lane] = v;
    }
}

__global__ void prep_all_kernel(const float* __restrict__ W1, const float* __restrict__ W2,
                                const float* __restrict__ W3, const float* __restrict__ W4)
{
    __shared__ float tile[16 * HIDD];
    switch (blockIdx.z) {
        case 0: prep_dev<HIDD, OBSD>(W1, OFF_L1, tile); break;
        case 1: prep_dev<HIDD, HIDD>(W2, OFF_L2, tile); break;
        case 2: prep_dev<HIDD, HIDD>(W3, OFF_L3, tile); break;
        default: prep_dev<ACTD, HIDD>(W4, OFF_L4, tile); break;
    }
}

// ---------------- fused main kernel ----------------
// A-fragment smem layout: idx(m,k) -> uint32 slot (m in [0,64))
//   mtile=m/16, ktile=k/16, a_lane=(m%8)*4+((k%8)/2), r=2*((k%16)>=8)+((m%16)>=8)
//   idx = ((mtile*16 + ktile)*32 + a_lane)*4 + r
// 8 warps: warp wn owns cols [wn*32, wn*32+32), computes all 4 mtiles (64 rows).

template<int K, bool ACT>
__device__ __forceinline__ void hidden_layer(
    unsigned char* smem,
    const uint4* __restrict__ bfr,
    const float* __restrict__ bv, const float* __restrict__ gv, const float* __restrict__ bev,
    int tid)
{
    const int lane = tid & 31;
    const int wn   = tid >> 5;
    uint32_t* ah = reinterpret_cast<uint32_t*>(smem + AFRAG_HI);
    uint32_t* al = reinterpret_cast<uint32_t*>(smem + AFRAG_LO);
    float* par  = reinterpret_cast<float*>(smem + PAR_OFF);
    float* red1 = reinterpret_cast<float*>(smem + RED1_OFF);
    float* red2 = reinterpret_cast<float*>(smem + RED2_OFF);

    for (int i = tid; i < 768; i += 256)
        par[i] = (i < 256) ? bv[i] : (i < 512 ? gv[i - 256] : bev[i - 512]);

    float acc[4][4][4];
#pragma unroll
    for (int q = 0; q < 4; q++)
#pragma unroll
        for (int nt = 0; nt < 4; nt++)
#pragma unroll
            for (int r = 0; r < 4; r++) acc[q][nt][r] = 0.f;

    const uint4* bwarp = bfr + (size_t)wn * 128 + lane;   // + kt*1024 + nt*32
    constexpr int KTN = K / 16;

    uint4 B[4];
#pragma unroll
    for (int nt = 0; nt < 4; nt++)
        B[nt] = __ldg(bwarp + nt * 32);

#pragma unroll 1
    for (int kt = 0; kt < KTN; kt++) {
        uint4 Bn[4];
        if (kt + 1 < KTN) {
#pragma unroll
            for (int nt = 0; nt < 4; nt++)
                Bn[nt] = __ldg(bwarp + (size_t)(kt + 1) * 1024 + nt * 32);
        }
#pragma unroll
        for (int q = 0; q < 4; q++) {
            uint4 Ah = reinterpret_cast<const uint4*>(ah)[(q * 16 + kt) * 32 + lane];
            uint4 Al = reinterpret_cast<const uint4*>(al)[(q * 16 + kt) * 32 + lane];
#pragma unroll
            for (int nt = 0; nt < 4; nt++) {
                mma16816(acc[q][nt], Ah, B[nt].x, B[nt].y);  // hi*hi
                mma16816(acc[q][nt], Ah, B[nt].z, B[nt].w);  // hi*lo
                mma16816(acc[q][nt], Al, B[nt].x, B[nt].y);  // lo*hi
            }
        }
#pragma unroll
        for (int nt = 0; nt < 4; nt++) B[nt] = Bn[nt];
    }
    __syncthreads();   // A reads done everywhere; par visible

    // bias + per-row partial sums (this warp's 32-col slice of all 64 rows)
#pragma unroll
    for (int q = 0; q < 4; q++) {
        float s1a = 0.f, s2a = 0.f, s1b = 0.f, s2b = 0.f;
#pragma unroll
        for (int nt = 0; nt < 4; nt++) {
            int n0 = wn * 32 + nt * 8 + (lane & 3) * 2;
            float b0 = par[n0], b1 = par[n0 + 1];
            float y0 = acc[q][nt][0] + b0, y1 = acc[q][nt][1] + b1;
            float y2 = acc[q][nt][2] + b0, y3 = acc[q][nt][3] + b1;
            acc[q][nt][0] = y0; acc[q][nt][1] = y1;
            acc[q][nt][2] = y2; acc[q][nt][3] = y3;
            s1a += y0 + y1; s2a = fmaf(y0, y0, fmaf(y1, y1, s2a));
            s1b += y2 + y3; s2b = fmaf(y2, y2, fmaf(y3, y3, s2b));
        }
        s1a += __shfl_xor_sync(~0u, s1a, 1); s1a += __shfl_xor_sync(~0u, s1a, 2);
        s2a += __shfl_xor_sync(~0u, s2a, 1); s2a += __shfl_xor_sync(~0u, s2a, 2);
        s1b += __shfl_xor_sync(~0u, s1b, 1); s1b += __shfl_xor_sync(~0u, s1b, 2);
        s2b += __shfl_xor_sync(~0u, s2b, 1); s2b += __shfl_xor_sync(~0u, s2b, 2);
        if ((lane & 3) == 0) {
            int m0 = q * 16 + (lane >> 2);
            red1[wn * 64 + m0]     = s1a; red2[wn * 64 + m0]     = s2a;
            red1[wn * 64 + m0 + 8] = s1b; red2[wn * 64 + m0 + 8] = s2b;
        }
    }
    __syncthreads();
    if (tid < 64) {
        float t1 = 0.f, t2 = 0.f;
#pragma unroll
        for (int w = 0; w < 8; w++) { t1 += red1[w * 64 + tid]; t2 += red2[w * 64 + tid]; }
        float mean = t1 * (1.f / 256.f);
        float var  = fmaf(-mean, mean, t2 * (1.f / 256.f));
        float rstd = rsqrtf(var + EPSV);
        red1[tid] = mean; red2[tid] = rstd;
    }
    __syncthreads();

    // normalize + activation + write next layer's A-fragments
#pragma unroll
    for (int q = 0; q < 4; q++) {
        int mA = q * 16 + (lane >> 2);
        float meanA = red1[mA],     rstdA = red2[mA];
        float meanB = red1[mA + 8], rstdB = red2[mA + 8];
#pragma unroll
        for (int nt = 0; nt < 4; nt++) {
            int n0 = wn * 32 + nt * 8 + (lane & 3) * 2;
            float g0 = par[256 + n0], g1 = par[257 + n0];
            float e0 = par[512 + n0], e1 = par[513 + n0];
            float y0 = fmaf((acc[q][nt][0] - meanA) * rstdA, g0, e0);
            float y1 = fmaf((acc[q][nt][1] - meanA) * rstdA, g1, e1);
            float y2 = fmaf((acc[q][nt][2] - meanB) * rstdB, g0, e0);
            float y3 = fmaf((acc[q][nt][3] - meanB) * rstdB, g1, e1);
            if (ACT) { y0 = elu1(y0); y1 = elu1(y1); y2 = elu1(y2); y3 = elu1(y3); }
            int aln = ((lane >> 2) << 2) + ((n0 & 7) >> 1);
            int rA  = ((n0 & 15) >= 8) ? 2 : 0;
            int idxb = ((q * 16 + (n0 >> 4)) * 32 + aln) * 4 + rA;
            uint32_t hp, lp;
            split_pack(y0, y1, hp, lp);
            ah[idxb] = hp; al[idxb] = lp;            // row mA   (r bit0 = 0)
            split_pack(y2, y3, hp, lp);
            ah[idxb + 1] = hp; al[idxb + 1] = lp;    // row mA+8 (r bit0 = 1)
        }
    }
    __syncthreads();
}

__device__ __forceinline__ void final_layer(
    unsigned char* smem, const uint4* __restrict__ bfr,
    const float* __restrict__ bv, const float* __restrict__ gv, const float* __restrict__ bev,
    float* __restrict__ out, int r0, int p, int tid)
{
    const int lane = tid & 31, wid = tid >> 5;   // warps 0-3 own rows [wid*16, +16)
    uint32_t* ah = reinterpret_cast<uint32_t*>(smem + AFRAG_HI);
    uint32_t* al = reinterpret_cast<uint32_t*>(smem + AFRAG_LO);
    float* par = reinterpret_cast<float*>(smem + PAR_OFF);

    for (int i = tid; i < 96; i += 256)
        par[i] = (i < 32) ? bv[i] : (i < 64 ? gv[i - 32] : bev[i - 64]);

    float acc[4][4];
#pragma unroll
    for (int nt = 0; nt < 4; nt++)
#pragma unroll
        for (int r = 0; r < 4; r++) acc[nt][r] = 0.f;

    if (wid < 4) {
#pragma unroll 1
        for (int kt = 0; kt < 16; kt++) {
            uint4 B[4];
#pragma unroll
            for (int nt = 0; nt < 4; nt++)
                B[nt] = __ldg(&bfr[((size_t)kt * 4 + nt) * 32 + lane]);
            uint4 Ah = reinterpret_cast<const uint4*>(ah)[(wid * 16 + kt) * 32 + lane];
            uint4 Al = reinterpret_cast<const uint4*>(al)[(wid * 16 + kt) * 32 + lane];
#pragma unroll
            for (int nt = 0; nt < 4; nt++) {
                mma16816(acc[nt], Ah, B[nt].x, B[nt].y);
                mma16816(acc[nt], Ah, B[nt].z, B[nt].w);
                mma16816(acc[nt], Al, B[nt].x, B[nt].y);
            }
        }
    }
    __syncthreads();   // par visible to all
    if (wid >= 4) return;

    float s1a = 0.f, s2a = 0.f, s1b = 0.f, s2b = 0.f;
#pragma unroll
    for (int nt = 0; nt < 4; nt++) {
        int n0 = nt * 8 + (lane & 3) * 2;
        float b0 = par[n0], b1 = par[n0 + 1];
        float y0 = acc[nt][0] + b0, y1 = acc[nt][1] + b1;
        float y2 = acc[nt][2] + b0, y3 = acc[nt][3] + b1;
        acc[nt][0] = y0; acc[nt][1] = y1; acc[nt][2] = y2; acc[nt][3] = y3;
        s1a += y0 + y1; s2a = fmaf(y0, y0, fmaf(y1, y1, s2a));
        s1b += y2 + y3; s2b = fmaf(y2, y2, fmaf(y3, y3, s2b));
    }
    s1a += __shfl_xor_sync(~0u, s1a, 1); s1a += __shfl_xor_sync(~0u, s1a, 2);
    s2a += __shfl_xor_sync(~0u, s2a, 1); s2a += __shfl_xor_sync(~0u, s2a, 2);
    s1b += __shfl_xor_sync(~0u, s1b, 1); s1b += __shfl_xor_sync(~0u, s1b, 2);
    s2b += __shfl_xor_sync(~0u, s2b, 1); s2b += __shfl_xor_sync(~0u, s2b, 2);
    const float meanA = s1a * (1.f / 32.f);
    const float rstdA = rsqrtf(fmaf(-meanA, meanA, s2a * (1.f / 32.f)) + EPSV);
    const float meanB = s1b * (1.f / 32.f);
    const float rstdB = rsqrtf(fmaf(-meanB, meanB, s2b * (1.f / 32.f)) + EPSV);

    const int mA = wid * 16 + (lane >> 2);
#pragma unroll
    for (int nt = 0; nt < 4; nt++) {
        int n0 = nt * 8 + (lane & 3) * 2;
        float g0 = par[32 + n0], g1 = par[33 + n0];
        float e0 = par[64 + n0], e1 = par[65 + n0];
        float2 o;
        o.x = fmaf((acc[nt][0] - meanA) * rstdA, g0, e0);
        o.y = fmaf((acc[nt][1] - meanA) * rstdA, g1, e1);
        *reinterpret_cast<float2*>(out + (size_t)(r0 + mA) * (NP * ACTD) + p * ACTD + n0) = o;
        o.x = fmaf((acc[nt][2] - meanB) * rstdB, g0, e0);
        o.y = fmaf((acc[nt][3] - meanB) * rstdB, g1, e1);
        *reinterpret_cast<float2*>(out + (size_t)(r0 + mA + 8) * (NP * ACTD) + p * ACTD + n0) = o;
    }
}

__global__ __launch_bounds__(256, 2)
void mlp_fused_kernel(
    const float* __restrict__ obs,
    const float* __restrict__ b1, const float* __restrict__ g1, const float* __restrict__ be1,
    const float* __restrict__ b2, const float* __restrict__ g2, const float* __restrict__ be2,
    const float* __restrict__ b3, const float* __restrict__ g3, const float* __restrict__ be3,
    const float* __restrict__ b4, const float* __restrict__ g4, const float* __restrict__ be4,
    float* __restrict__ out)
{
    extern __shared__ unsigned char smem[];
    const int tid = threadIdx.x;
    const int p   = blockIdx.y;
    const int r0  = blockIdx.x * MT;
    uint32_t* ah = reinterpret_cast<uint32_t*>(smem + AFRAG_HI);
    uint32_t* al = reinterpret_cast<uint32_t*>(smem + AFRAG_LO);

    // stage observation tile as split-bf16 A-fragments (256 threads, 64 rows)
    {
        const int m = tid >> 2, q4 = tid & 3;
        const float* orow = obs + (size_t)(r0 + m) * OBSD + q4 * 32;
#pragma unroll
        for (int j = 0; j < 16; j++) {
            float2 v = reinterpret_cast<const float2*>(orow)[j];
            uint32_t hp, lp; split_pack(v.x, v.y, hp, lp);
            int k = q4 * 32 + j * 2;
            int aln = ((m & 7) << 2) + ((k & 7) >> 1);
            int r = (((k & 15) >= 8) ? 2 : 0) + (((m & 15) >= 8) ? 1 : 0);
            int idx = (((m >> 4) * 16 + (k >> 4)) * 32 + aln) * 4 + r;
            ah[idx] = hp; al[idx] = lp;
        }
    }
    __syncthreads();

    hidden_layer<OBSD, true>(smem,
        reinterpret_cast<const uint4*>(g_wimg + OFF_L1 + (size_t)p * L1_BYTES),
        b1 + p * HIDD, g1 + p * HIDD, be1 + p * HIDD, tid);
    hidden_layer<HIDD, true>(smem,
        reinterpret_cast<const uint4*>(g_wimg + OFF_L2 + (size_t)p * L2_BYTES),
        b2 + p * HIDD, g2 + p * HIDD, be2 + p * HIDD, tid);
    hidden_layer<HIDD, true>(smem,
        reinterpret_cast<const uint4*>(g_wimg + OFF_L3 + (size_t)p * L2_BYTES),
        b3 + p * HIDD, g3 + p * HIDD, be3 + p * HIDD, tid);
    final_layer(smem,
        reinterpret_cast<const uint4*>(g_wimg + OFF_L4 + (size_t)p * L4_BYTES),
        b4 + p * ACTD, g4 + p * ACTD, be4 + p * ACTD, out, r0, p, tid);
}

// ---------------- launch ----------------
extern "C" void kernel_launch(void* const* d_in, const int* in_sizes, int n_in,
                              void* d_out, int out_size)
{
    const float* obs = (const float*)d_in[0];
    const float* W1  = (const float*)d_in[1];
    const float* b1  = (const float*)d_in[2];
    const float* g1  = (const float*)d_in[3];
    const float* be1 = (const float*)d_in[4];
    const float* W2  = (const float*)d_in[5];
    const float* b2  = (const float*)d_in[6];
    const float* g2  = (const float*)d_in[7];
    const float* be2 = (const float*)d_in[8];
    const float* W3  = (const float*)d_in[9];
    const float* b3  = (const float*)d_in[10];
    const float* g3  = (const float*)d_in[11];
    const float* be3 = (const float*)d_in[12];
    const float* W4  = (const float*)d_in[13];
    const float* b4  = (const float*)d_in[14];
    const float* g4  = (const float*)d_in[15];
    const float* be4 = (const float*)d_in[16];
    float* out = (float*)d_out;

    prep_all_kernel<<<dim3(NP, HIDD / 16, 4), 256>>>(W1, W2, W3, W4);

    cudaFuncSetAttribute(mlp_fused_kernel,
                         cudaFuncAttributeMaxDynamicSharedMemorySize, DSMEM_BYTES);
    dim3 grid(NB / MT, NP);
    mlp_fused_kernel<<<grid, 256, DSMEM_BYTES>>>(
        obs, b1, g1, be1, b2, g2, be2, b3, g3, be3, b4, g4, be4, out);
}